// round 8
// baseline (speedup 1.0000x reference)
#include <cuda_runtime.h>

// Problem dims
#define B_   4
#define N_   512
#define D_   512
#define H_   16
#define DH_  32
#define P_   64
#define FINAL_ELEMS (B_ * N_ * D_)      // final [B,N,D]; then attn [B,H,N,N]
#define RSQRT_DH 0.17677669529663687f   // 1/sqrt(32)

// Scratch (no cudaMalloc allowed)
__device__ __align__(16) float g_q[B_ * H_ * N_ * DH_];   // [B,H,N,DH]
__device__ __align__(16) float g_k[B_ * H_ * N_ * DH_];
__device__ __align__(16) float g_v[B_ * H_ * N_ * DH_];
__device__ __align__(16) float g_o[B_ * N_ * D_];         // [B,N,D] context before Wo

// Packed fp32x2 FMA (FFMA2) — doubles fp32 FMA throughput on sm_103a.
__device__ __forceinline__ float2 ffma2(float2 a, float2 b, float2 c) {
    float2 d;
    asm("fma.rn.f32x2 %0, %1, %2, %3;"
        : "=l"(reinterpret_cast<unsigned long long &>(d))
        : "l"(reinterpret_cast<unsigned long long &>(a)),
          "l"(reinterpret_cast<unsigned long long &>(b)),
          "l"(reinterpret_cast<unsigned long long &>(c)));
    return d;
}

// ===========================================================================
// GEMM core: 128x64 tile, 256 threads, 8x4 microtile, BK=16, double-buffered.
// ===========================================================================
#define APAD 132

// ---------------------------------------------------------------------------
// K1: QKV projection (unchanged from R7).
// ---------------------------------------------------------------------------
__global__ __launch_bounds__(256) void qkv_kernel(
    const float* __restrict__ x, const float* __restrict__ Wq,
    const float* __restrict__ Wk, const float* __restrict__ Wv) {
    __shared__ __align__(16) float As[2][16][APAD];
    __shared__ __align__(16) float Bs[2][16][64];

    int tid = threadIdx.x;
    int tx = tid & 15, ty = tid >> 4;
    int row0 = blockIdx.y << 7;
    int col0 = blockIdx.x << 6;
    int mat = col0 >> 9;
    int wcol0 = col0 & 511;
    const float* W = (mat == 0) ? Wq : ((mat == 1) ? Wk : Wv);

    int arow = tid >> 2, akq = (tid & 3) << 2;
    int brow = tid >> 4, bcol = (tid & 15) << 2;

    float2 acc[8][2];
#pragma unroll
    for (int i = 0; i < 8; i++) { acc[i][0] = make_float2(0.f, 0.f); acc[i][1] = make_float2(0.f, 0.f); }

    {
        float4 a0 = *(const float4*)(x + (size_t)(row0 + arow) * 512 + akq);
        float4 a1 = *(const float4*)(x + (size_t)(row0 + arow + 64) * 512 + akq);
        As[0][akq + 0][arow] = a0.x; As[0][akq + 1][arow] = a0.y;
        As[0][akq + 2][arow] = a0.z; As[0][akq + 3][arow] = a0.w;
        As[0][akq + 0][arow + 64] = a1.x; As[0][akq + 1][arow + 64] = a1.y;
        As[0][akq + 2][arow + 64] = a1.z; As[0][akq + 3][arow + 64] = a1.w;
        *(float4*)&Bs[0][brow][bcol] = *(const float4*)(W + (size_t)brow * 512 + wcol0 + bcol);
    }
    __syncthreads();

    int buf = 0;
    for (int kk = 0; kk < 512; kk += 16) {
        float4 pa0, pa1, pb0;
        bool pf = (kk + 16) < 512;
        if (pf) {
            pa0 = *(const float4*)(x + (size_t)(row0 + arow) * 512 + kk + 16 + akq);
            pa1 = *(const float4*)(x + (size_t)(row0 + arow + 64) * 512 + kk + 16 + akq);
            pb0 = *(const float4*)(W + (size_t)(kk + 16 + brow) * 512 + wcol0 + bcol);
        }
#pragma unroll
        for (int k2 = 0; k2 < 16; k2++) {
            float4 a0 = *(float4*)&As[buf][k2][ty << 3];
            float4 a1 = *(float4*)&As[buf][k2][(ty << 3) + 4];
            float4 bv = *(float4*)&Bs[buf][k2][tx << 2];
            float2 b01 = make_float2(bv.x, bv.y);
            float2 b23 = make_float2(bv.z, bv.w);
            acc[0][0] = ffma2(make_float2(a0.x, a0.x), b01, acc[0][0]);
            acc[0][1] = ffma2(make_float2(a0.x, a0.x), b23, acc[0][1]);
            acc[1][0] = ffma2(make_float2(a0.y, a0.y), b01, acc[1][0]);
            acc[1][1] = ffma2(make_float2(a0.y, a0.y), b23, acc[1][1]);
            acc[2][0] = ffma2(make_float2(a0.z, a0.z), b01, acc[2][0]);
            acc[2][1] = ffma2(make_float2(a0.z, a0.z), b23, acc[2][1]);
            acc[3][0] = ffma2(make_float2(a0.w, a0.w), b01, acc[3][0]);
            acc[3][1] = ffma2(make_float2(a0.w, a0.w), b23, acc[3][1]);
            acc[4][0] = ffma2(make_float2(a1.x, a1.x), b01, acc[4][0]);
            acc[4][1] = ffma2(make_float2(a1.x, a1.x), b23, acc[4][1]);
            acc[5][0] = ffma2(make_float2(a1.y, a1.y), b01, acc[5][0]);
            acc[5][1] = ffma2(make_float2(a1.y, a1.y), b23, acc[5][1]);
            acc[6][0] = ffma2(make_float2(a1.z, a1.z), b01, acc[6][0]);
            acc[6][1] = ffma2(make_float2(a1.z, a1.z), b23, acc[6][1]);
            acc[7][0] = ffma2(make_float2(a1.w, a1.w), b01, acc[7][0]);
            acc[7][1] = ffma2(make_float2(a1.w, a1.w), b23, acc[7][1]);
        }
        if (pf) {
            int nb = buf ^ 1;
            As[nb][akq + 0][arow] = pa0.x; As[nb][akq + 1][arow] = pa0.y;
            As[nb][akq + 2][arow] = pa0.z; As[nb][akq + 3][arow] = pa0.w;
            As[nb][akq + 0][arow + 64] = pa1.x; As[nb][akq + 1][arow + 64] = pa1.y;
            As[nb][akq + 2][arow + 64] = pa1.z; As[nb][akq + 3][arow + 64] = pa1.w;
            *(float4*)&Bs[nb][brow][bcol] = pb0;
        }
        __syncthreads();
        buf ^= 1;
    }

    float* dst = (mat == 0) ? g_q : ((mat == 1) ? g_k : g_v);
    int c = wcol0 + (tx << 2);
    int h = c >> 5, dh = c & 31;
#pragma unroll
    for (int i = 0; i < 8; i++) {
        int r = row0 + (ty << 3) + i;
        int bb = r >> 9, n = r & 511;
        float4 v = make_float4(acc[i][0].x, acc[i][0].y, acc[i][1].x, acc[i][1].y);
        *(float4*)&dst[(((size_t)(bb * H_) + h) * N_ + n) * DH_ + dh] = v;
    }
}

// ---------------------------------------------------------------------------
// K2: FUSED bias + QK^T + softmax + AV.
// Block = (hgroup of 4 heads, b, 16-row n-tile). 256 threads.
// Bias never touches HBM; K/V streamed in 64-m chunks, double-buffered smem.
// Grid x = hgroup (fastest) so the 4 blocks sharing a pair_bias slice are
// adjacent -> L2 reuse of the masked pair_bias read.
// ---------------------------------------------------------------------------
#define FH 4
#define FN 16
#define SCST 520
#define KC 64
#define KCPAD 36
#define KCBUF (FH * KC * KCPAD)            // 9216 floats per buffer
#define OFF_KC   (FH * FN * SCST)          // 33280
#define OFF_QS   (OFF_KC + 2 * KCBUF)      // 51712
#define OFF_WPB  (OFF_QS + FH * FN * DH_)  // 53760
#define OFF_MOK  (OFF_WPB + P_ * 4)        // 54016
#define FUS_FLOATS (OFF_MOK + 512)         // 54528
#define FUS_BYTES  (FUS_FLOATS * 4)        // 218112

__global__ __launch_bounds__(256, 1) void fused_bias_attn_kernel(
    const float* __restrict__ pb, const float* __restrict__ Wp,
    const int* __restrict__ mask, float* __restrict__ attn) {
    extern __shared__ __align__(16) float sm[];
    float*  scores = sm;                       // [4][16][520]
    float*  Kc     = sm + OFF_KC;              // [2][4][64][36]
    float*  qs     = sm + OFF_QS;              // [4][16][32]
    float4* Wpb    = (float4*)(sm + OFF_WPB);  // [64] (4 heads per p)
    float*  mok    = sm + OFF_MOK;             // [512]

    int tid = threadIdx.x;
    int hg = blockIdx.x;                 // 0..3
    int bn = blockIdx.y;                 // b*32 + ntile
    int b = bn >> 5, nt = bn & 31;
    int n0 = nt << 4, h0 = hg << 2;

    // ---- phase 0: small loads ----
    mok[tid]       = mask[(b << 9) + tid]       ? 1.f : 0.f;
    mok[tid + 256] = mask[(b << 9) + tid + 256] ? 1.f : 0.f;
    if (tid < 64) Wpb[tid] = *(const float4*)(Wp + tid * H_ + h0);
#pragma unroll
    for (int i = 0; i < 2; i++) {
        int f = tid + (i << 8);              // 0..511 float4s of qs
        int h = f >> 7, rem = f & 127, n = rem >> 3, d4 = rem & 7;
        ((float4*)qs)[f] = *(const float4*)(
            g_q + (((size_t)(b * H_ + h0 + h) * N_) + n0 + n) * DH_ + (d4 << 2));
    }
    __syncthreads();

    // ---- phase 1: pair bias -> scores (4 heads per element) ----
    {
        int n = tid >> 4, mg = tid & 15;
        float qm = mok[n0 + n];
        const float* pbrow = pb + (((size_t)(b * N_) + n0 + n) * N_) * P_;
#pragma unroll 4
        for (int j = 0; j < 32; j++) {
            int m = mg + (j << 4);
            float2 a01 = make_float2(0.f, 0.f), a23 = make_float2(0.f, 0.f);
            if (qm != 0.f && mok[m] != 0.f) {
                const float4* pbv = (const float4*)(pbrow + (size_t)m * P_);
#pragma unroll
                for (int p4 = 0; p4 < 16; p4++) {
                    float4 v = pbv[p4];
                    float4 w0 = Wpb[(p4 << 2) + 0];
                    float4 w1 = Wpb[(p4 << 2) + 1];
                    float4 w2 = Wpb[(p4 << 2) + 2];
                    float4 w3 = Wpb[(p4 << 2) + 3];
                    a01 = ffma2(make_float2(v.x, v.x), make_float2(w0.x, w0.y), a01);
                    a23 = ffma2(make_float2(v.x, v.x), make_float2(w0.z, w0.w), a23);
                    a01 = ffma2(make_float2(v.y, v.y), make_float2(w1.x, w1.y), a01);
                    a23 = ffma2(make_float2(v.y, v.y), make_float2(w1.z, w1.w), a23);
                    a01 = ffma2(make_float2(v.z, v.z), make_float2(w2.x, w2.y), a01);
                    a23 = ffma2(make_float2(v.z, v.z), make_float2(w2.z, w2.w), a23);
                    a01 = ffma2(make_float2(v.w, v.w), make_float2(w3.x, w3.y), a01);
                    a23 = ffma2(make_float2(v.w, v.w), make_float2(w3.z, w3.w), a23);
                }
            }
            int base = n * SCST + m;
            scores[base]                  = a01.x;
            scores[base + FN * SCST]      = a01.y;
            scores[base + 2 * FN * SCST]  = a23.x;
            scores[base + 3 * FN * SCST]  = a23.y;
        }
    }
    __syncthreads();

    // ---- phase 2: scores += qK^T/sqrt(DH); K chunks of 64 m, double-buffered
    int h  = tid >> 6;              // 0..3
    int ng = (tid >> 3) & 7;        // 2 n rows per thread
    int mg = tid & 7;

    float2 q2[2][16];
#pragma unroll
    for (int nn = 0; nn < 2; nn++)
#pragma unroll
        for (int t = 0; t < 16; t++)
            q2[nn][t] = *(float2*)&qs[((h << 4) + (ng << 1) + nn) * DH_ + (t << 1)];

    // preload chunk 0
    {
#pragma unroll
        for (int i = 0; i < 8; i++) {
            int f = tid + (i << 8);
            int hl = f >> 9, rem = f & 511, ml = rem >> 3, d4 = rem & 7;
            *(float4*)&Kc[hl * (KC * KCPAD) + ml * KCPAD + (d4 << 2)] =
                *(const float4*)(g_k + (((size_t)(b * H_ + h0 + hl) * N_) + ml) * DH_ + (d4 << 2));
        }
    }
    __syncthreads();

    for (int c = 0; c < 8; c++) {
        float4 pf[8];
        if (c < 7) {
            int mc = (c + 1) << 6;
#pragma unroll
            for (int i = 0; i < 8; i++) {
                int f = tid + (i << 8);
                int hl = f >> 9, rem = f & 511, ml = rem >> 3, d4 = rem & 7;
                pf[i] = *(const float4*)(
                    g_k + (((size_t)(b * H_ + h0 + hl) * N_) + mc + ml) * DH_ + (d4 << 2));
            }
        }
        const float* kb = Kc + (c & 1) * KCBUF + h * (KC * KCPAD);
#pragma unroll
        for (int j = 0; j < 8; j++) {
            int m = mg + (j << 3);
            const float* kr = kb + m * KCPAD;
            float4 k4[8];
#pragma unroll
            for (int d4 = 0; d4 < 8; d4++) k4[d4] = *(const float4*)&kr[d4 << 2];
#pragma unroll
            for (int nn = 0; nn < 2; nn++) {
                float2 a = make_float2(0.f, 0.f);
#pragma unroll
                for (int d4 = 0; d4 < 8; d4++) {
                    a = ffma2(q2[nn][2 * d4],     make_float2(k4[d4].x, k4[d4].y), a);
                    a = ffma2(q2[nn][2 * d4 + 1], make_float2(k4[d4].z, k4[d4].w), a);
                }
                int idx = ((h << 4) + (ng << 1) + nn) * SCST + (c << 6) + m;
                scores[idx] += (a.x + a.y) * RSQRT_DH;
            }
        }
        if (c < 7) {
            int nbuf = (c + 1) & 1;
#pragma unroll
            for (int i = 0; i < 8; i++) {
                int f = tid + (i << 8);
                int hl = f >> 9, rem = f & 511, ml = rem >> 3, d4 = rem & 7;
                *(float4*)&Kc[nbuf * KCBUF + hl * (KC * KCPAD) + ml * KCPAD + (d4 << 2)] = pf[i];
            }
        }
        __syncthreads();
    }

    // ---- phase 3: key-mask + softmax; write attn; probs stay in scores ----
    {
        int w = tid >> 5, lane = tid & 31;
#pragma unroll
        for (int j = 0; j < 8; j++) {
            int row = (w << 3) + j;              // 0..63 == h*16+n
            float* srow = &scores[row * SCST];
            float s[16];
            float mx = -3.0e38f;
#pragma unroll
            for (int i = 0; i < 16; i++) {
                int m = lane + (i << 5);
                float v = srow[m];
                v = (mok[m] != 0.f) ? v : -1e6f;
                s[i] = v;
                mx = fmaxf(mx, v);
            }
#pragma unroll
            for (int o = 16; o > 0; o >>= 1) mx = fmaxf(mx, __shfl_xor_sync(0xffffffffu, mx, o));
            float sum = 0.f;
#pragma unroll
            for (int i = 0; i < 16; i++) { s[i] = __expf(s[i] - mx); sum += s[i]; }
#pragma unroll
            for (int o = 16; o > 0; o >>= 1) sum += __shfl_xor_sync(0xffffffffu, sum, o);
            float inv = 1.0f / sum;
            int h3 = row >> 4, n3 = row & 15;
            size_t abase = (((size_t)(b * H_ + h0 + h3) * N_) + n0 + n3) * N_;
#pragma unroll
            for (int i = 0; i < 16; i++) {
                float pv = s[i] * inv;
                srow[lane + (i << 5)] = pv;
                attn[abase + lane + (i << 5)] = pv;
            }
        }
    }
    __syncthreads();

    // ---- phase 4: out = P @ V; V chunks of 64 m, double-buffered ----
    int dg = tid & 7;                            // 4 d's per thread
    float2 o00 = make_float2(0.f, 0.f), o01 = make_float2(0.f, 0.f);
    float2 o10 = make_float2(0.f, 0.f), o11 = make_float2(0.f, 0.f);

    {
#pragma unroll
        for (int i = 0; i < 8; i++) {
            int f = tid + (i << 8);
            int hl = f >> 9, rem = f & 511, ml = rem >> 3, d4 = rem & 7;
            *(float4*)&Kc[hl * (KC * KCPAD) + ml * KCPAD + (d4 << 2)] =
                *(const float4*)(g_v + (((size_t)(b * H_ + h0 + hl) * N_) + ml) * DH_ + (d4 << 2));
        }
    }
    __syncthreads();

    for (int c = 0; c < 8; c++) {
        float4 pf[8];
        if (c < 7) {
            int mc = (c + 1) << 6;
#pragma unroll
            for (int i = 0; i < 8; i++) {
                int f = tid + (i << 8);
                int hl = f >> 9, rem = f & 511, ml = rem >> 3, d4 = rem & 7;
                pf[i] = *(const float4*)(
                    g_v + (((size_t)(b * H_ + h0 + hl) * N_) + mc + ml) * DH_ + (d4 << 2));
            }
        }
        const float* vb = Kc + (c & 1) * KCBUF + h * (KC * KCPAD);
        const float* p0row = &scores[((h << 4) + (ng << 1) + 0) * SCST + (c << 6)];
        const float* p1row = &scores[((h << 4) + (ng << 1) + 1) * SCST + (c << 6)];
#pragma unroll
        for (int m4 = 0; m4 < 64; m4 += 4) {
            float4 p0 = *(const float4*)&p0row[m4];
            float4 p1 = *(const float4*)&p1row[m4];
            float4 v0 = *(const float4*)&vb[(m4 + 0) * KCPAD + (dg << 2)];
            float4 v1 = *(const float4*)&vb[(m4 + 1) * KCPAD + (dg << 2)];
            float4 v2 = *(const float4*)&vb[(m4 + 2) * KCPAD + (dg << 2)];
            float4 v3 = *(const float4*)&vb[(m4 + 3) * KCPAD + (dg << 2)];
            o00 = ffma2(make_float2(p0.x, p0.x), make_float2(v0.x, v0.y), o00);
            o01 = ffma2(make_float2(p0.x, p0.x), make_float2(v0.z, v0.w), o01);
            o10 = ffma2(make_float2(p1.x, p1.x), make_float2(v0.x, v0.y), o10);
            o11 = ffma2(make_float2(p1.x, p1.x), make_float2(v0.z, v0.w), o11);
            o00 = ffma2(make_float2(p0.y, p0.y), make_float2(v1.x, v1.y), o00);
            o01 = ffma2(make_float2(p0.y, p0.y), make_float2(v1.z, v1.w), o01);
            o10 = ffma2(make_float2(p1.y, p1.y), make_float2(v1.x, v1.y), o10);
            o11 = ffma2(make_float2(p1.y, p1.y), make_float2(v1.z, v1.w), o11);
            o00 = ffma2(make_float2(p0.z, p0.z), make_float2(v2.x, v2.y), o00);
            o01 = ffma2(make_float2(p0.z, p0.z), make_float2(v2.z, v2.w), o01);
            o10 = ffma2(make_float2(p1.z, p1.z), make_float2(v2.x, v2.y), o10);
            o11 = ffma2(make_float2(p1.z, p1.z), make_float2(v2.z, v2.w), o11);
            o00 = ffma2(make_float2(p0.w, p0.w), make_float2(v3.x, v3.y), o00);
            o01 = ffma2(make_float2(p0.w, p0.w), make_float2(v3.z, v3.w), o01);
            o10 = ffma2(make_float2(p1.w, p1.w), make_float2(v3.x, v3.y), o10);
            o11 = ffma2(make_float2(p1.w, p1.w), make_float2(v3.z, v3.w), o11);
        }
        if (c < 7) {
            int nbuf = (c + 1) & 1;
#pragma unroll
            for (int i = 0; i < 8; i++) {
                int f = tid + (i << 8);
                int hl = f >> 9, rem = f & 511, ml = rem >> 3, d4 = rem & 7;
                *(float4*)&Kc[nbuf * KCBUF + hl * (KC * KCPAD) + ml * KCPAD + (d4 << 2)] = pf[i];
            }
        }
        __syncthreads();
    }

    // store: g_o[b][n0+n][ (h0+h)*32 + dg*4 .. +3 ]
    {
        int n_a = (ng << 1) + 0, n_b = (ng << 1) + 1;
        *(float4*)&g_o[(((size_t)(b * N_) + n0 + n_a) * D_) + ((h0 + h) << 5) + (dg << 2)] =
            make_float4(o00.x, o00.y, o01.x, o01.y);
        *(float4*)&g_o[(((size_t)(b * N_) + n0 + n_b) * D_) + ((h0 + h) << 5) + (dg << 2)] =
            make_float4(o10.x, o10.y, o11.x, o11.y);
    }
}

// ---------------------------------------------------------------------------
// K3: final = (g_o @ Wo), zero masked query rows (unchanged from R7).
// ---------------------------------------------------------------------------
__global__ __launch_bounds__(256) void outproj_kernel(
    const float* __restrict__ Wo, const int* __restrict__ mask,
    float* __restrict__ outp) {
    __shared__ __align__(16) float As[2][16][APAD];
    __shared__ __align__(16) float Bs[2][16][64];

    int tid = threadIdx.x;
    int tx = tid & 15, ty = tid >> 4;
    int row0 = blockIdx.y << 7;
    int col0 = blockIdx.x << 6;

    int arow = tid >> 2, akq = (tid & 3) << 2;
    int brow = tid >> 4, bcol = (tid & 15) << 2;

    float2 acc[8][2];
#pragma unroll
    for (int i = 0; i < 8; i++) { acc[i][0] = make_float2(0.f, 0.f); acc[i][1] = make_float2(0.f, 0.f); }

    {
        float4 a0 = *(const float4*)(g_o + (size_t)(row0 + arow) * 512 + akq);
        float4 a1 = *(const float4*)(g_o + (size_t)(row0 + arow + 64) * 512 + akq);
        As[0][akq + 0][arow] = a0.x; As[0][akq + 1][arow] = a0.y;
        As[0][akq + 2][arow] = a0.z; As[0][akq + 3][arow] = a0.w;
        As[0][akq + 0][arow + 64] = a1.x; As[0][akq + 1][arow + 64] = a1.y;
        As[0][akq + 2][arow + 64] = a1.z; As[0][akq + 3][arow + 64] = a1.w;
        *(float4*)&Bs[0][brow][bcol] = *(const float4*)(Wo + (size_t)brow * 512 + col0 + bcol);
    }
    __syncthreads();

    int buf = 0;
    for (int kk = 0; kk < 512; kk += 16) {
        float4 pa0, pa1, pb0;
        bool pf = (kk + 16) < 512;
        if (pf) {
            pa0 = *(const float4*)(g_o + (size_t)(row0 + arow) * 512 + kk + 16 + akq);
            pa1 = *(const float4*)(g_o + (size_t)(row0 + arow + 64) * 512 + kk + 16 + akq);
            pb0 = *(const float4*)(Wo + (size_t)(kk + 16 + brow) * 512 + col0 + bcol);
        }
#pragma unroll
        for (int k2 = 0; k2 < 16; k2++) {
            float4 a0 = *(float4*)&As[buf][k2][ty << 3];
            float4 a1 = *(float4*)&As[buf][k2][(ty << 3) + 4];
            float4 bv = *(float4*)&Bs[buf][k2][tx << 2];
            float2 b01 = make_float2(bv.x, bv.y);
            float2 b23 = make_float2(bv.z, bv.w);
            acc[0][0] = ffma2(make_float2(a0.x, a0.x), b01, acc[0][0]);
            acc[0][1] = ffma2(make_float2(a0.x, a0.x), b23, acc[0][1]);
            acc[1][0] = ffma2(make_float2(a0.y, a0.y), b01, acc[1][0]);
            acc[1][1] = ffma2(make_float2(a0.y, a0.y), b23, acc[1][1]);
            acc[2][0] = ffma2(make_float2(a0.z, a0.z), b01, acc[2][0]);
            acc[2][1] = ffma2(make_float2(a0.z, a0.z), b23, acc[2][1]);
            acc[3][0] = ffma2(make_float2(a0.w, a0.w), b01, acc[3][0]);
            acc[3][1] = ffma2(make_float2(a0.w, a0.w), b23, acc[3][1]);
            acc[4][0] = ffma2(make_float2(a1.x, a1.x), b01, acc[4][0]);
            acc[4][1] = ffma2(make_float2(a1.x, a1.x), b23, acc[4][1]);
            acc[5][0] = ffma2(make_float2(a1.y, a1.y), b01, acc[5][0]);
            acc[5][1] = ffma2(make_float2(a1.y, a1.y), b23, acc[5][1]);
            acc[6][0] = ffma2(make_float2(a1.z, a1.z), b01, acc[6][0]);
            acc[6][1] = ffma2(make_float2(a1.z, a1.z), b23, acc[6][1]);
            acc[7][0] = ffma2(make_float2(a1.w, a1.w), b01, acc[7][0]);
            acc[7][1] = ffma2(make_float2(a1.w, a1.w), b23, acc[7][1]);
        }
        if (pf) {
            int nb = buf ^ 1;
            As[nb][akq + 0][arow] = pa0.x; As[nb][akq + 1][arow] = pa0.y;
            As[nb][akq + 2][arow] = pa0.z; As[nb][akq + 3][arow] = pa0.w;
            As[nb][akq + 0][arow + 64] = pa1.x; As[nb][akq + 1][arow + 64] = pa1.y;
            As[nb][akq + 2][arow + 64] = pa1.z; As[nb][akq + 3][arow + 64] = pa1.w;
            *(float4*)&Bs[nb][brow][bcol] = pb0;
        }
        __syncthreads();
        buf ^= 1;
    }

    int c = col0 + (tx << 2);
#pragma unroll
    for (int i = 0; i < 8; i++) {
        int r = row0 + (ty << 3) + i;
        float msk = mask[r] ? 1.f : 0.f;
        float4 v = make_float4(acc[i][0].x * msk, acc[i][0].y * msk,
                               acc[i][1].x * msk, acc[i][1].y * msk);
        *(float4*)&outp[(size_t)r * 512 + c] = v;
    }
}

// ---------------------------------------------------------------------------
extern "C" void kernel_launch(void* const* d_in, const int* in_sizes, int n_in,
                              void* d_out, int out_size) {
    const float* x    = (const float*)d_in[0];
    const float* pb   = (const float*)d_in[1];
    const float* Wq   = (const float*)d_in[2];
    const float* Wk   = (const float*)d_in[3];
    const float* Wv   = (const float*)d_in[4];
    const float* Wo   = (const float*)d_in[5];
    const float* Wp   = (const float*)d_in[6];
    const int*   mask = (const int*)d_in[7];

    float* out  = (float*)d_out;
    float* attn = out + FINAL_ELEMS;

    static int inited = 0;
    if (!inited) {
        cudaFuncSetAttribute(fused_bias_attn_kernel,
                             cudaFuncAttributeMaxDynamicSharedMemorySize,
                             FUS_BYTES);
        inited = 1;
    }

    qkv_kernel<<<dim3(24, 16), 256>>>(x, Wq, Wk, Wv);
    fused_bias_attn_kernel<<<dim3(4, B_ * 32), 256, FUS_BYTES>>>(pb, Wp, mask, attn);
    outproj_kernel<<<dim3(8, 16), 256>>>(Wo, mask, out);
}

// round 9
// speedup vs baseline: 1.1906x; 1.1906x over previous
#include <cuda_runtime.h>

// Problem dims
#define B_   4
#define N_   512
#define D_   512
#define H_   16
#define DH_  32
#define P_   64
#define FINAL_ELEMS (B_ * N_ * D_)      // final [B,N,D]; then attn [B,H,N,N]
#define RSQRT_DH 0.17677669529663687f   // 1/sqrt(32)

// Scratch (no cudaMalloc allowed)
__device__ __align__(16) float g_q[B_ * H_ * N_ * DH_];   // [B,H,N,DH]
__device__ __align__(16) float g_k[B_ * H_ * N_ * DH_];
__device__ __align__(16) float g_v[B_ * H_ * N_ * DH_];
__device__ __align__(16) float g_o[B_ * N_ * D_];         // [B,N,D] context before Wo

// Packed fp32x2 FMA (FFMA2) — doubles fp32 FMA throughput on sm_103a.
__device__ __forceinline__ float2 ffma2(float2 a, float2 b, float2 c) {
    float2 d;
    asm("fma.rn.f32x2 %0, %1, %2, %3;"
        : "=l"(reinterpret_cast<unsigned long long &>(d))
        : "l"(reinterpret_cast<unsigned long long &>(a)),
          "l"(reinterpret_cast<unsigned long long &>(b)),
          "l"(reinterpret_cast<unsigned long long &>(c)));
    return d;
}

// ===========================================================================
// GEMM core: 128x64 tile, 256 threads, 8x4 microtile, BK=16, double-buffered.
// ===========================================================================
#define APAD 132

// ---------------------------------------------------------------------------
// K1: QKV projection (unchanged — 74 us, 54.6% fma).
// ---------------------------------------------------------------------------
__global__ __launch_bounds__(256) void qkv_kernel(
    const float* __restrict__ x, const float* __restrict__ Wq,
    const float* __restrict__ Wk, const float* __restrict__ Wv) {
    __shared__ __align__(16) float As[2][16][APAD];
    __shared__ __align__(16) float Bs[2][16][64];

    int tid = threadIdx.x;
    int tx = tid & 15, ty = tid >> 4;
    int row0 = blockIdx.y << 7;
    int col0 = blockIdx.x << 6;
    int mat = col0 >> 9;
    int wcol0 = col0 & 511;
    const float* W = (mat == 0) ? Wq : ((mat == 1) ? Wk : Wv);

    int arow = tid >> 2, akq = (tid & 3) << 2;
    int brow = tid >> 4, bcol = (tid & 15) << 2;

    float2 acc[8][2];
#pragma unroll
    for (int i = 0; i < 8; i++) { acc[i][0] = make_float2(0.f, 0.f); acc[i][1] = make_float2(0.f, 0.f); }

    {
        float4 a0 = *(const float4*)(x + (size_t)(row0 + arow) * 512 + akq);
        float4 a1 = *(const float4*)(x + (size_t)(row0 + arow + 64) * 512 + akq);
        As[0][akq + 0][arow] = a0.x; As[0][akq + 1][arow] = a0.y;
        As[0][akq + 2][arow] = a0.z; As[0][akq + 3][arow] = a0.w;
        As[0][akq + 0][arow + 64] = a1.x; As[0][akq + 1][arow + 64] = a1.y;
        As[0][akq + 2][arow + 64] = a1.z; As[0][akq + 3][arow + 64] = a1.w;
        *(float4*)&Bs[0][brow][bcol] = *(const float4*)(W + (size_t)brow * 512 + wcol0 + bcol);
    }
    __syncthreads();

    int buf = 0;
    for (int kk = 0; kk < 512; kk += 16) {
        float4 pa0, pa1, pb0;
        bool pf = (kk + 16) < 512;
        if (pf) {
            pa0 = *(const float4*)(x + (size_t)(row0 + arow) * 512 + kk + 16 + akq);
            pa1 = *(const float4*)(x + (size_t)(row0 + arow + 64) * 512 + kk + 16 + akq);
            pb0 = *(const float4*)(W + (size_t)(kk + 16 + brow) * 512 + wcol0 + bcol);
        }
#pragma unroll
        for (int k2 = 0; k2 < 16; k2++) {
            float4 a0 = *(float4*)&As[buf][k2][ty << 3];
            float4 a1 = *(float4*)&As[buf][k2][(ty << 3) + 4];
            float4 bv = *(float4*)&Bs[buf][k2][tx << 2];
            float2 b01 = make_float2(bv.x, bv.y);
            float2 b23 = make_float2(bv.z, bv.w);
            acc[0][0] = ffma2(make_float2(a0.x, a0.x), b01, acc[0][0]);
            acc[0][1] = ffma2(make_float2(a0.x, a0.x), b23, acc[0][1]);
            acc[1][0] = ffma2(make_float2(a0.y, a0.y), b01, acc[1][0]);
            acc[1][1] = ffma2(make_float2(a0.y, a0.y), b23, acc[1][1]);
            acc[2][0] = ffma2(make_float2(a0.z, a0.z), b01, acc[2][0]);
            acc[2][1] = ffma2(make_float2(a0.z, a0.z), b23, acc[2][1]);
            acc[3][0] = ffma2(make_float2(a0.w, a0.w), b01, acc[3][0]);
            acc[3][1] = ffma2(make_float2(a0.w, a0.w), b23, acc[3][1]);
            acc[4][0] = ffma2(make_float2(a1.x, a1.x), b01, acc[4][0]);
            acc[4][1] = ffma2(make_float2(a1.x, a1.x), b23, acc[4][1]);
            acc[5][0] = ffma2(make_float2(a1.y, a1.y), b01, acc[5][0]);
            acc[5][1] = ffma2(make_float2(a1.y, a1.y), b23, acc[5][1]);
            acc[6][0] = ffma2(make_float2(a1.z, a1.z), b01, acc[6][0]);
            acc[6][1] = ffma2(make_float2(a1.z, a1.z), b23, acc[6][1]);
            acc[7][0] = ffma2(make_float2(a1.w, a1.w), b01, acc[7][0]);
            acc[7][1] = ffma2(make_float2(a1.w, a1.w), b23, acc[7][1]);
        }
        if (pf) {
            int nb = buf ^ 1;
            As[nb][akq + 0][arow] = pa0.x; As[nb][akq + 1][arow] = pa0.y;
            As[nb][akq + 2][arow] = pa0.z; As[nb][akq + 3][arow] = pa0.w;
            As[nb][akq + 0][arow + 64] = pa1.x; As[nb][akq + 1][arow + 64] = pa1.y;
            As[nb][akq + 2][arow + 64] = pa1.z; As[nb][akq + 3][arow + 64] = pa1.w;
            *(float4*)&Bs[nb][brow][bcol] = pb0;
        }
        __syncthreads();
        buf ^= 1;
    }

    float* dst = (mat == 0) ? g_q : ((mat == 1) ? g_k : g_v);
    int c = wcol0 + (tx << 2);
    int h = c >> 5, dh = c & 31;
#pragma unroll
    for (int i = 0; i < 8; i++) {
        int r = row0 + (ty << 3) + i;
        int bb = r >> 9, n = r & 511;
        float4 v = make_float4(acc[i][0].x, acc[i][0].y, acc[i][1].x, acc[i][1].y);
        *(float4*)&dst[(((size_t)(bb * H_) + h) * N_ + n) * DH_ + dh] = v;
    }
}

// ---------------------------------------------------------------------------
// K2: bias -> attn region, STG.128 stores.
// Block per (b,n); 256 threads = 2 hgroups(8 h) x 128 mgroups(4 m).
// ---------------------------------------------------------------------------
__device__ __forceinline__ void bias_step(float2 acc[4][4],
    float a0, float a1, float a2, float a3, const float2* __restrict__ w) {
#pragma unroll
    for (int hp = 0; hp < 4; hp++) {
        acc[0][hp] = ffma2(make_float2(a0, a0), w[hp], acc[0][hp]);
        acc[1][hp] = ffma2(make_float2(a1, a1), w[hp], acc[1][hp]);
        acc[2][hp] = ffma2(make_float2(a2, a2), w[hp], acc[2][hp]);
        acc[3][hp] = ffma2(make_float2(a3, a3), w[hp], acc[3][hp]);
    }
}

__global__ __launch_bounds__(256) void bias_kernel(
    const float* __restrict__ pb, const float* __restrict__ Wp,
    const int* __restrict__ mask, float* __restrict__ attn) {
    __shared__ __align__(16) float Wps[P_ * H_];   // [p][h]
    __shared__ float mok[N_];
    int tid = threadIdx.x;
#pragma unroll
    for (int i = 0; i < 4; i++) Wps[tid + (i << 8)] = Wp[tid + (i << 8)];
    int bn = blockIdx.x;
    int bb = bn >> 9, n = bn & 511;
    mok[tid]       = mask[(bb << 9) + tid]       ? 1.f : 0.f;
    mok[tid + 256] = mask[(bb << 9) + tid + 256] ? 1.f : 0.f;
    __syncthreads();

    int mg = tid & 127, hg = tid >> 7;
    int m0 = mg << 2, h0 = hg << 3;
    float qm = mok[n];

    float2 acc[4][4];
#pragma unroll
    for (int mi = 0; mi < 4; mi++)
#pragma unroll
        for (int hp = 0; hp < 4; hp++) acc[mi][hp] = make_float2(0.f, 0.f);

    float mm0 = qm * mok[m0], mm1 = qm * mok[m0 + 1];
    float mm2 = qm * mok[m0 + 2], mm3 = qm * mok[m0 + 3];

    if (mm0 + mm1 + mm2 + mm3 > 0.f) {
        const float* pbase = pb + ((((size_t)bn) * N_) + m0) * P_;
        const float4* pv0 = (const float4*)(pbase);
        const float4* pv1 = (const float4*)(pbase + P_);
        const float4* pv2 = (const float4*)(pbase + 2 * P_);
        const float4* pv3 = (const float4*)(pbase + 3 * P_);
#pragma unroll
        for (int p4 = 0; p4 < 16; p4++) {
            float4 v0 = pv0[p4], v1 = pv1[p4], v2 = pv2[p4], v3 = pv3[p4];
            const float2* wb = (const float2*)&Wps[(p4 << 2) * H_ + h0];
            bias_step(acc, v0.x, v1.x, v2.x, v3.x, wb);
            bias_step(acc, v0.y, v1.y, v2.y, v3.y, wb + 8);
            bias_step(acc, v0.z, v1.z, v2.z, v3.z, wb + 16);
            bias_step(acc, v0.w, v1.w, v2.w, v3.w, wb + 24);
        }
        // per-m pair mask
#pragma unroll
        for (int hp = 0; hp < 4; hp++) {
            acc[0][hp] = make_float2(acc[0][hp].x * mm0, acc[0][hp].y * mm0);
            acc[1][hp] = make_float2(acc[1][hp].x * mm1, acc[1][hp].y * mm1);
            acc[2][hp] = make_float2(acc[2][hp].x * mm2, acc[2][hp].y * mm2);
            acc[3][hp] = make_float2(acc[3][hp].x * mm3, acc[3][hp].y * mm3);
        }
    }

#pragma unroll
    for (int hp = 0; hp < 4; hp++) {
        float4 sx = make_float4(acc[0][hp].x, acc[1][hp].x, acc[2][hp].x, acc[3][hp].x);
        float4 sy = make_float4(acc[0][hp].y, acc[1][hp].y, acc[2][hp].y, acc[3][hp].y);
        *(float4*)&attn[(((size_t)(bb * H_ + h0 + (hp << 1) + 0)) * N_ + n) * N_ + m0] = sx;
        *(float4*)&attn[(((size_t)(bb * H_ + h0 + (hp << 1) + 1)) * N_ + n) * N_ + m0] = sy;
    }
}

// ---------------------------------------------------------------------------
// K3: attention per (b,h, 32-row tile). 2-row register blocking in QK and PV
// (K/V smem loads shared across the row pair; row-pair in lane LSB for
// conflict-free dedup). Bias-add + mask folded into the softmax pass
// (coalesced attn gmem read). 256 threads.
// ---------------------------------------------------------------------------
#define ATR 32
#define PSST 520
#define OFF_VS 18432                       // 512*36
#define OFF_PS (OFF_VS + 18432)
#define OFF_QS (OFF_PS + ATR * PSST)       // 53504
#define OFF_MK (OFF_QS + ATR * DH_)        // 54528
#define K3_FLOATS (OFF_MK + 512)           // 55040
#define K3_SMEM_BYTES (K3_FLOATS * 4)      // 220160

__global__ __launch_bounds__(256, 1) void attn_kernel(
    const int* __restrict__ mask, float* __restrict__ attn) {
    extern __shared__ __align__(16) float sm[];
    float* Ks  = sm;                 // [512][36]
    float* Vs  = sm + OFF_VS;        // [512][36]
    float* Ps  = sm + OFF_PS;        // [32][520]
    float* qs  = sm + OFF_QS;        // [32][32]
    float* mok = sm + OFF_MK;        // [512]

    int tid = threadIdx.x;
    int bh = blockIdx.y;
    int bb = bh >> 4;
    int n0 = blockIdx.x << 5;

    const float* gk = g_k + (size_t)bh * (N_ * DH_);
    const float* gv = g_v + (size_t)bh * (N_ * DH_);
    const float* gq = g_q + (size_t)bh * (N_ * DH_);

#pragma unroll
    for (int j = 0; j < 16; j++) {
        int i4 = tid + (j << 8);
        int m = i4 >> 3, kq = (i4 & 7) << 2;
        *(float4*)&Ks[m * 36 + kq] = *(const float4*)(gk + ((size_t)i4 << 2));
        *(float4*)&Vs[m * 36 + kq] = *(const float4*)(gv + ((size_t)i4 << 2));
    }
    {
        int row = tid >> 3, d4 = tid & 7;
        *(float4*)&qs[(row << 5) + (d4 << 2)] =
            *(const float4*)(gq + (size_t)(n0 + row) * DH_ + (d4 << 2));
    }
    mok[tid]       = mask[(bb << 9) + tid]       ? 1.f : 0.f;
    mok[tid + 256] = mask[(bb << 9) + tid + 256] ? 1.f : 0.f;
    __syncthreads();

    // ---- QK: rp in lane LSB (dedup), cg = (tid>>1)&15 ----
    {
        int rp = ((tid >> 5) << 1) | (tid & 1);    // 0..15 row-pairs
        int cg = (tid >> 1) & 15;
        int r0 = rp << 1;

        float2 q2[2][16];
#pragma unroll
        for (int r = 0; r < 2; r++)
#pragma unroll
            for (int t = 0; t < 16; t++)
                q2[r][t] = *(float2*)&qs[((r0 + r) << 5) + (t << 1)];

        float acc[2][32];
#pragma unroll
        for (int j = 0; j < 32; j++) {
            int m = (j << 4) + cg;
            const float* kr = &Ks[m * 36];
            float4 k4[8];
#pragma unroll
            for (int d4 = 0; d4 < 8; d4++) k4[d4] = *(const float4*)&kr[d4 << 2];
#pragma unroll
            for (int r = 0; r < 2; r++) {
                float2 t = make_float2(0.f, 0.f);
#pragma unroll
                for (int d4 = 0; d4 < 8; d4++) {
                    t = ffma2(q2[r][2 * d4],     make_float2(k4[d4].x, k4[d4].y), t);
                    t = ffma2(q2[r][2 * d4 + 1], make_float2(k4[d4].z, k4[d4].w), t);
                }
                acc[r][j] = t.x + t.y;
            }
        }
#pragma unroll
        for (int r = 0; r < 2; r++)
#pragma unroll
            for (int j = 0; j < 32; j++)
                Ps[(r0 + r) * PSST + (j << 4) + cg] = acc[r][j];
    }
    __syncthreads();

    // ---- softmax: warp per 4 rows; scale + bias(gmem) + mask folded in ----
    {
        int w = tid >> 5, lane = tid & 31;
#pragma unroll
        for (int jr = 0; jr < 4; jr++) {
            int row = (w << 2) + jr;
            float* srow = &Ps[row * PSST];
            size_t abase = ((size_t)bh * N_ + n0 + row) * N_;
            float s[16];
            float mx = -3.0e38f;
#pragma unroll
            for (int i = 0; i < 16; i++) {
                int m = lane + (i << 5);
                float v = srow[m] * RSQRT_DH + attn[abase + m];
                v = (mok[m] != 0.f) ? v : -1e6f;
                s[i] = v;
                mx = fmaxf(mx, v);
            }
#pragma unroll
            for (int o = 16; o > 0; o >>= 1) mx = fmaxf(mx, __shfl_xor_sync(0xffffffffu, mx, o));
            float sum = 0.f;
#pragma unroll
            for (int i = 0; i < 16; i++) { s[i] = __expf(s[i] - mx); sum += s[i]; }
#pragma unroll
            for (int o = 16; o > 0; o >>= 1) sum += __shfl_xor_sync(0xffffffffu, sum, o);
            float inv = 1.0f / sum;
#pragma unroll
            for (int i = 0; i < 16; i++) {
                float pv = s[i] * inv;
                int m = lane + (i << 5);
                srow[m] = pv;
                attn[abase + m] = pv;
            }
        }
    }
    __syncthreads();

    // ---- PV: 2 rows x d-pair per thread; V loads dedup'd across row pair ----
    {
        int rp = tid >> 4, dg = tid & 15;
        int r0 = rp << 1;
        const float* p0 = &Ps[r0 * PSST];
        const float* p1 = &Ps[(r0 + 1) * PSST];
        float2 o0 = make_float2(0.f, 0.f), o1 = make_float2(0.f, 0.f);
#pragma unroll 8
        for (int m4 = 0; m4 < 128; m4++) {
            int m = m4 << 2;
            float4 pa = *(const float4*)&p0[m];
            float4 pc = *(const float4*)&p1[m];
            float2 v0 = *(const float2*)&Vs[(m + 0) * 36 + (dg << 1)];
            float2 v1 = *(const float2*)&Vs[(m + 1) * 36 + (dg << 1)];
            float2 v2 = *(const float2*)&Vs[(m + 2) * 36 + (dg << 1)];
            float2 v3 = *(const float2*)&Vs[(m + 3) * 36 + (dg << 1)];
            o0 = ffma2(make_float2(pa.x, pa.x), v0, o0);
            o1 = ffma2(make_float2(pc.x, pc.x), v0, o1);
            o0 = ffma2(make_float2(pa.y, pa.y), v1, o0);
            o1 = ffma2(make_float2(pc.y, pc.y), v1, o1);
            o0 = ffma2(make_float2(pa.z, pa.z), v2, o0);
            o1 = ffma2(make_float2(pc.z, pc.z), v2, o1);
            o0 = ffma2(make_float2(pa.w, pa.w), v3, o0);
            o1 = ffma2(make_float2(pc.w, pc.w), v3, o1);
        }
        int h = bh & 15;
        *(float2*)&g_o[((size_t)(bb * N_ + n0 + r0)) * D_ + (h << 5) + (dg << 1)] = o0;
        *(float2*)&g_o[((size_t)(bb * N_ + n0 + r0 + 1)) * D_ + (h << 5) + (dg << 1)] = o1;
    }
}

// ---------------------------------------------------------------------------
// K4: final = (g_o @ Wo), zero masked query rows (unchanged).
// ---------------------------------------------------------------------------
__global__ __launch_bounds__(256) void outproj_kernel(
    const float* __restrict__ Wo, const int* __restrict__ mask,
    float* __restrict__ outp) {
    __shared__ __align__(16) float As[2][16][APAD];
    __shared__ __align__(16) float Bs[2][16][64];

    int tid = threadIdx.x;
    int tx = tid & 15, ty = tid >> 4;
    int row0 = blockIdx.y << 7;
    int col0 = blockIdx.x << 6;

    int arow = tid >> 2, akq = (tid & 3) << 2;
    int brow = tid >> 4, bcol = (tid & 15) << 2;

    float2 acc[8][2];
#pragma unroll
    for (int i = 0; i < 8; i++) { acc[i][0] = make_float2(0.f, 0.f); acc[i][1] = make_float2(0.f, 0.f); }

    {
        float4 a0 = *(const float4*)(g_o + (size_t)(row0 + arow) * 512 + akq);
        float4 a1 = *(const float4*)(g_o + (size_t)(row0 + arow + 64) * 512 + akq);
        As[0][akq + 0][arow] = a0.x; As[0][akq + 1][arow] = a0.y;
        As[0][akq + 2][arow] = a0.z; As[0][akq + 3][arow] = a0.w;
        As[0][akq + 0][arow + 64] = a1.x; As[0][akq + 1][arow + 64] = a1.y;
        As[0][akq + 2][arow + 64] = a1.z; As[0][akq + 3][arow + 64] = a1.w;
        *(float4*)&Bs[0][brow][bcol] = *(const float4*)(Wo + (size_t)brow * 512 + col0 + bcol);
    }
    __syncthreads();

    int buf = 0;
    for (int kk = 0; kk < 512; kk += 16) {
        float4 pa0, pa1, pb0;
        bool pf = (kk + 16) < 512;
        if (pf) {
            pa0 = *(const float4*)(g_o + (size_t)(row0 + arow) * 512 + kk + 16 + akq);
            pa1 = *(const float4*)(g_o + (size_t)(row0 + arow + 64) * 512 + kk + 16 + akq);
            pb0 = *(const float4*)(Wo + (size_t)(kk + 16 + brow) * 512 + col0 + bcol);
        }
#pragma unroll
        for (int k2 = 0; k2 < 16; k2++) {
            float4 a0 = *(float4*)&As[buf][k2][ty << 3];
            float4 a1 = *(float4*)&As[buf][k2][(ty << 3) + 4];
            float4 bv = *(float4*)&Bs[buf][k2][tx << 2];
            float2 b01 = make_float2(bv.x, bv.y);
            float2 b23 = make_float2(bv.z, bv.w);
            acc[0][0] = ffma2(make_float2(a0.x, a0.x), b01, acc[0][0]);
            acc[0][1] = ffma2(make_float2(a0.x, a0.x), b23, acc[0][1]);
            acc[1][0] = ffma2(make_float2(a0.y, a0.y), b01, acc[1][0]);
            acc[1][1] = ffma2(make_float2(a0.y, a0.y), b23, acc[1][1]);
            acc[2][0] = ffma2(make_float2(a0.z, a0.z), b01, acc[2][0]);
            acc[2][1] = ffma2(make_float2(a0.z, a0.z), b23, acc[2][1]);
            acc[3][0] = ffma2(make_float2(a0.w, a0.w), b01, acc[3][0]);
            acc[3][1] = ffma2(make_float2(a0.w, a0.w), b23, acc[3][1]);
            acc[4][0] = ffma2(make_float2(a1.x, a1.x), b01, acc[4][0]);
            acc[4][1] = ffma2(make_float2(a1.x, a1.x), b23, acc[4][1]);
            acc[5][0] = ffma2(make_float2(a1.y, a1.y), b01, acc[5][0]);
            acc[5][1] = ffma2(make_float2(a1.y, a1.y), b23, acc[5][1]);
            acc[6][0] = ffma2(make_float2(a1.z, a1.z), b01, acc[6][0]);
            acc[6][1] = ffma2(make_float2(a1.z, a1.z), b23, acc[6][1]);
            acc[7][0] = ffma2(make_float2(a1.w, a1.w), b01, acc[7][0]);
            acc[7][1] = ffma2(make_float2(a1.w, a1.w), b23, acc[7][1]);
        }
        if (pf) {
            int nb = buf ^ 1;
            As[nb][akq + 0][arow] = pa0.x; As[nb][akq + 1][arow] = pa0.y;
            As[nb][akq + 2][arow] = pa0.z; As[nb][akq + 3][arow] = pa0.w;
            As[nb][akq + 0][arow + 64] = pa1.x; As[nb][akq + 1][arow + 64] = pa1.y;
            As[nb][akq + 2][arow + 64] = pa1.z; As[nb][akq + 3][arow + 64] = pa1.w;
            *(float4*)&Bs[nb][brow][bcol] = pb0;
        }
        __syncthreads();
        buf ^= 1;
    }

    int c = col0 + (tx << 2);
#pragma unroll
    for (int i = 0; i < 8; i++) {
        int r = row0 + (ty << 3) + i;
        float msk = mask[r] ? 1.f : 0.f;
        float4 v = make_float4(acc[i][0].x * msk, acc[i][0].y * msk,
                               acc[i][1].x * msk, acc[i][1].y * msk);
        *(float4*)&outp[(size_t)r * 512 + c] = v;
    }
}

// ---------------------------------------------------------------------------
extern "C" void kernel_launch(void* const* d_in, const int* in_sizes, int n_in,
                              void* d_out, int out_size) {
    const float* x    = (const float*)d_in[0];
    const float* pb   = (const float*)d_in[1];
    const float* Wq   = (const float*)d_in[2];
    const float* Wk   = (const float*)d_in[3];
    const float* Wv   = (const float*)d_in[4];
    const float* Wo   = (const float*)d_in[5];
    const float* Wp   = (const float*)d_in[6];
    const int*   mask = (const int*)d_in[7];

    float* out  = (float*)d_out;
    float* attn = out + FINAL_ELEMS;

    static int inited = 0;
    if (!inited) {
        cudaFuncSetAttribute(attn_kernel,
                             cudaFuncAttributeMaxDynamicSharedMemorySize,
                             K3_SMEM_BYTES);
        inited = 1;
    }

    qkv_kernel<<<dim3(24, 16), 256>>>(x, Wq, Wk, Wv);
    bias_kernel<<<B_ * N_, 256>>>(pb, Wp, mask, attn);
    attn_kernel<<<dim3(N_ / ATR, B_ * H_), 256, K3_SMEM_BYTES>>>(mask, attn);
    outproj_kernel<<<dim3(8, 16), 256>>>(Wo, mask, out);
}